// round 16
// baseline (speedup 1.0000x reference)
#include <cuda_runtime.h>
#include <cstdint>

#define NROWS 8192
#define L2E 1.44269504088896340736f

// ---------------- scratch ----------------
__device__ __align__(16) unsigned g_mask[NROWS * 256];   // 8 MB bitmask
__device__ __align__(16) float g_h[4 * NROWS * 64];      // per-head h = x@Wh
__device__ __align__(16) float g_xcat[NROWS * 256];      // concat LR(head outputs)
__device__ __align__(16) float g_h2[NROWS * 16];         // xcat@Wo
__device__ __align__(16) float g_f1[5 * NROWS];          // f1 * log2e per layer
__device__ __align__(16) float g_f2[5 * NROWS];          // f2 * log2e per layer
__device__ __align__(16) float2 g_b2[5 * NROWS];         // {2^f2, 2^(0.2 f2)}
__device__ unsigned g_gmaxu[5];                          // encoded global max of f2
__device__ __align__(16) float g_hp[16 * NROWS * 64];    // heads partials
__device__ __align__(16) float g_hpZ[16 * NROWS];
__device__ __align__(16) float g_part[8 * NROWS * 16];   // final-layer partials
__device__ __align__(16) float g_partZ[8 * NROWS];

// ---------------- helpers ----------------
__device__ __forceinline__ float ex2f(float x) {
    float r; asm("ex2.approx.ftz.f32 %0, %1;" : "=f"(r) : "f"(x)); return r;
}
__device__ __forceinline__ unsigned long long pk2(float a, float b) {
    unsigned long long r; asm("mov.b64 %0, {%1, %2};" : "=l"(r) : "f"(a), "f"(b)); return r;
}
__device__ __forceinline__ void up2(unsigned long long v, float& a, float& b) {
    asm("mov.b64 {%0, %1}, %2;" : "=f"(a), "=f"(b) : "l"(v));
}
__device__ __forceinline__ void fma2(unsigned long long& d, unsigned long long a, unsigned long long b) {
    asm("fma.rn.f32x2 %0, %1, %2, %0;" : "+l"(d) : "l"(a), "l"(b));
}
__device__ __forceinline__ void lds2u64(const float* p, unsigned long long& a, unsigned long long& b) {
    unsigned sa = (unsigned)__cvta_generic_to_shared(p);
    asm volatile("ld.shared.v2.u64 {%0, %1}, [%2];" : "=l"(a), "=l"(b) : "r"(sa));
}
__device__ __forceinline__ unsigned long long lds1u64(const float* p) {
    unsigned sa = (unsigned)__cvta_generic_to_shared(p);
    unsigned long long r;
    asm volatile("ld.shared.b64 %0, [%1];" : "=l"(r) : "r"(sa));
    return r;
}
// order-preserving fp32 <-> uint for atomicMax
__device__ __forceinline__ unsigned encf(float f) {
    unsigned u = __float_as_uint(f);
    return (u & 0x80000000u) ? ~u : (u | 0x80000000u);
}
__device__ __forceinline__ float decf(unsigned e) {
    unsigned u = (e & 0x80000000u) ? (e ^ 0x80000000u) : ~e;
    return __uint_as_float(u);
}

// ---------------- 1) pack adjacency ----------------
__global__ void __launch_bounds__(256) pack_adj_kernel(const int* __restrict__ adj) {
    const int lane = threadIdx.x & 31;
    const int wid = (blockIdx.x * blockDim.x + threadIdx.x) >> 5;
    const int nWarps = (gridDim.x * blockDim.x) >> 5;
    for (int w = wid; w < NROWS * 256; w += nWarps) {
        int v = adj[(size_t)w * 32 + lane];
        unsigned b = __ballot_sync(0xffffffffu, v > 0);
        if (lane == 0) g_mask[w] = b;
    }
}

// ---------------- 2) h = x @ Wh[head] (FFMA2 row-pair), inits g_gmaxu --------
__global__ void __launch_bounds__(256) gemm64_kernel(const float* __restrict__ X,
                                                     const float* __restrict__ WhAll) {
    const int head = blockIdx.y;
    const float* W = WhAll + head * (512 * 64);
    float* C = g_h + head * (NROWS * 64);
    const int r0 = blockIdx.x * 64;
    const int tid = threadIdx.x;
    if (blockIdx.x == 0 && blockIdx.y == 0 && tid < 5) g_gmaxu[tid] = 0u;
    __shared__ float4 As4[512];
    __shared__ float4 Bs4[512];
    float* As = (float*)As4;
    float* Bs = (float*)Bs4;
    const int tr = tid >> 4, tc = tid & 15;
    const int lm = tid & 63, kg = tid >> 6;
    unsigned long long accP[2][4];
#pragma unroll
    for (int p = 0; p < 2; p++)
#pragma unroll
        for (int j = 0; j < 4; j++) accP[p][j] = 0ull;

    for (int kt = 0; kt < 512; kt += 32) {
        __syncthreads();
        const float* xb = X + (size_t)(r0 + lm) * 512 + kt + kg * 8;
        float4 a0 = ((const float4*)xb)[0];
        float4 a1 = ((const float4*)xb)[1];
        As[(kg * 8 + 0) * 64 + lm] = a0.x; As[(kg * 8 + 1) * 64 + lm] = a0.y;
        As[(kg * 8 + 2) * 64 + lm] = a0.z; As[(kg * 8 + 3) * 64 + lm] = a0.w;
        As[(kg * 8 + 4) * 64 + lm] = a1.x; As[(kg * 8 + 5) * 64 + lm] = a1.y;
        As[(kg * 8 + 6) * 64 + lm] = a1.z; As[(kg * 8 + 7) * 64 + lm] = a1.w;
        const float4* wsrc = (const float4*)(W + kt * 64);
        Bs4[tid] = wsrc[tid];
        Bs4[tid + 256] = wsrc[tid + 256];
        __syncthreads();
#pragma unroll
        for (int kk = 0; kk < 32; kk++) {
            unsigned long long ap0, ap1;
            lds2u64(As + kk * 64 + tr * 4, ap0, ap1);
            float4 bv = *(const float4*)(Bs + kk * 64 + tc * 4);
            unsigned long long b0 = pk2(bv.x, bv.x);
            unsigned long long b1 = pk2(bv.y, bv.y);
            unsigned long long b2 = pk2(bv.z, bv.z);
            unsigned long long b3 = pk2(bv.w, bv.w);
            fma2(accP[0][0], ap0, b0); fma2(accP[0][1], ap0, b1);
            fma2(accP[0][2], ap0, b2); fma2(accP[0][3], ap0, b3);
            fma2(accP[1][0], ap1, b0); fma2(accP[1][1], ap1, b1);
            fma2(accP[1][2], ap1, b2); fma2(accP[1][3], ap1, b3);
        }
    }
#pragma unroll
    for (int p = 0; p < 2; p++) {
        float lo[4], hi[4];
#pragma unroll
        for (int j = 0; j < 4; j++) up2(accP[p][j], lo[j], hi[j]);
        *(float4*)(C + (size_t)(r0 + tr * 4 + 2 * p) * 64 + tc * 4) =
            make_float4(lo[0], lo[1], lo[2], lo[3]);
        *(float4*)(C + (size_t)(r0 + tr * 4 + 2 * p + 1) * 64 + tc * 4) =
            make_float4(hi[0], hi[1], hi[2], hi[3]);
    }
}

// ---------------- 3) f1/f2 + B values + block-reduced gmax ----------------
__global__ void __launch_bounds__(256) f1f2_heads_kernel(const float* __restrict__ ah) {
    const int head = blockIdx.y;
    const float* H = g_h + head * (NROWS * 64);
    const float* a = ah + head * 128;
    const int lane = threadIdx.x & 31;
    const int warp = threadIdx.x >> 5;
    const int row = blockIdx.x * 8 + warp;
    __shared__ float bmax[8];
    float h0 = H[row * 64 + lane], h1 = H[row * 64 + 32 + lane];
    float s1 = h0 * a[lane] + h1 * a[32 + lane];
    float s2 = h0 * a[64 + lane] + h1 * a[96 + lane];
#pragma unroll
    for (int off = 16; off; off >>= 1) {
        s1 += __shfl_xor_sync(0xffffffffu, s1, off);
        s2 += __shfl_xor_sync(0xffffffffu, s2, off);
    }
    float f2v = s2 * L2E;
    if (lane == 0) {
        g_f1[head * NROWS + row] = s1 * L2E;
        g_f2[head * NROWS + row] = f2v;
        g_b2[head * NROWS + row] = make_float2(ex2f(f2v), ex2f(0.2f * f2v));
        bmax[warp] = f2v;
    }
    __syncthreads();
    if (threadIdx.x == 0) {
        float m = bmax[0];
#pragma unroll
        for (int i = 1; i < 8; i++) m = fmaxf(m, bmax[i]);
        atomicMax(&g_gmaxu[head], encf(m));
    }
}

__global__ void __launch_bounds__(256) f1f2_final_kernel(const float* __restrict__ ao) {
    const int lane = threadIdx.x & 31;
    const int warp = threadIdx.x >> 5;
    const int row = blockIdx.x * 8 + warp;
    __shared__ float bmax[8];
    float s1 = 0.f, s2 = 0.f;
    if (lane < 16) {
        float h = g_h2[row * 16 + lane];
        s1 = h * ao[lane];
        s2 = h * ao[16 + lane];
    }
#pragma unroll
    for (int off = 16; off; off >>= 1) {
        s1 += __shfl_xor_sync(0xffffffffu, s1, off);
        s2 += __shfl_xor_sync(0xffffffffu, s2, off);
    }
    float f2v = s2 * L2E;
    if (lane == 0) {
        g_f1[4 * NROWS + row] = s1 * L2E;
        g_f2[4 * NROWS + row] = f2v;
        g_b2[4 * NROWS + row] = make_float2(ex2f(f2v), ex2f(0.2f * f2v));
        bmax[warp] = f2v;
    }
    __syncthreads();
    if (threadIdx.x == 0) {
        float m = bmax[0];
#pragma unroll
        for (int i = 1; i < 8; i++) m = fmaxf(m, bmax[i]);
        atomicMax(&g_gmaxu[4], encf(m));
    }
}

// ---------------- 5) head attention (z folded into k-loop, no P re-read) -----
#define PSTRIDE 132
__global__ void __launch_bounds__(128, 4) attn_heads_gemm() {
    const int head = blockIdx.y;
    const int split = blockIdx.z;
    const int r0 = blockIdx.x * 128;
    const int tid = threadIdx.x;
    const int tr = tid >> 3;
    const int tc = tid & 7;
    const int jj = tid & 31;
    const int quarter = tid >> 5;

    __shared__ float Ps[32 * PSTRIDE];
    __shared__ float Hs[32 * 64];
    __shared__ float Aps[128], Ams[128];
    __shared__ unsigned mws[128];

    {
        float f1v = g_f1[head * NROWS + r0 + tid];
        float gm = decf(g_gmaxu[head]);
        float s = f1v + gm;
        float m = fmaxf(s, 0.2f * s);
        Aps[tid] = ex2f(f1v - m);
        Ams[tid] = ex2f(0.2f * f1v - m);
    }

    unsigned long long acc[8][4];
#pragma unroll
    for (int r = 0; r < 8; r++)
#pragma unroll
        for (int c = 0; c < 4; c++) acc[r][c] = 0ull;
    float zs[8];
#pragma unroll
    for (int r = 0; r < 8; r++) zs[r] = 0.f;

    const int jbase = split * 2048;
    const float4* hsrc = (const float4*)(g_h + (size_t)head * NROWS * 64);
    const size_t mrow = (size_t)(r0 + tid) * 256;

    float4 hpre[4];
    {
        const float4* s = hsrc + (size_t)jbase * 16;
#pragma unroll
        for (int v = 0; v < 4; v++) hpre[v] = s[tid + 128 * v];
    }
    unsigned mwpre = g_mask[mrow + (jbase >> 5)];
    float2 bvpre = g_b2[head * NROWS + jbase + jj];

    for (int ch = 0; ch < 64; ch++) {
        const int j0 = jbase + ch * 32;
        __syncthreads();
        {
            float4* dst = (float4*)Hs;
#pragma unroll
            for (int v = 0; v < 4; v++) dst[tid + 128 * v] = hpre[v];
        }
        mws[tid] = mwpre;
        const float Bpr = bvpre.x, Bmr = bvpre.y;
        __syncthreads();
        {
            const int jn = (ch < 63) ? j0 + 32 : j0;
            const float4* s = hsrc + (size_t)jn * 16;
#pragma unroll
            for (int v = 0; v < 4; v++) hpre[v] = s[tid + 128 * v];
            mwpre = g_mask[mrow + (jn >> 5)];
            bvpre = g_b2[head * NROWS + jn + jj];
        }
        {
            const int i0 = quarter * 32;
            float* prow = Ps + jj * PSTRIDE;
#pragma unroll
            for (int ib = 0; ib < 32; ib += 4) {
                float pv[4];
#pragma unroll
                for (int ii = 0; ii < 4; ii++) {
                    const int i = i0 + ib + ii;
                    float v = fmaxf(Aps[i] * Bpr, Ams[i] * Bmr);
                    pv[ii] = ((mws[i] >> jj) & 1u) ? v : 0.f;
                }
                *(float4*)(prow + i0 + ib) = make_float4(pv[0], pv[1], pv[2], pv[3]);
            }
        }
        __syncthreads();
#pragma unroll 2
        for (int k = 0; k < 32; k++) {
            float4 pa = *(const float4*)(Ps + k * PSTRIDE + tr * 8);
            float4 pb = *(const float4*)(Ps + k * PSTRIDE + tr * 8 + 4);
            unsigned long long h0, h1, h2, h3;
            lds2u64(Hs + k * 64 + tc * 8, h0, h1);
            lds2u64(Hs + k * 64 + tc * 8 + 4, h2, h3);
            // z accumulation from registers (replaces the 16KB/chunk P re-read)
            zs[0] += pa.x; zs[1] += pa.y; zs[2] += pa.z; zs[3] += pa.w;
            zs[4] += pb.x; zs[5] += pb.y; zs[6] += pb.z; zs[7] += pb.w;
            unsigned long long p2[8];
            p2[0] = pk2(pa.x, pa.x); p2[1] = pk2(pa.y, pa.y);
            p2[2] = pk2(pa.z, pa.z); p2[3] = pk2(pa.w, pa.w);
            p2[4] = pk2(pb.x, pb.x); p2[5] = pk2(pb.y, pb.y);
            p2[6] = pk2(pb.z, pb.z); p2[7] = pk2(pb.w, pb.w);
#pragma unroll
            for (int r = 0; r < 8; r++) {
                fma2(acc[r][0], p2[r], h0);
                fma2(acc[r][1], p2[r], h1);
                fma2(acc[r][2], p2[r], h2);
                fma2(acc[r][3], p2[r], h3);
            }
        }
    }
    const int base = (split * 4 + head) * NROWS;
#pragma unroll
    for (int r = 0; r < 8; r++) {
        const int row = r0 + tr * 8 + r;
        float v[8];
        up2(acc[r][0], v[0], v[1]);
        up2(acc[r][1], v[2], v[3]);
        up2(acc[r][2], v[4], v[5]);
        up2(acc[r][3], v[6], v[7]);
        float* op = g_hp + ((size_t)base + row) * 64 + tc * 8;
        *(float4*)op = make_float4(v[0], v[1], v[2], v[3]);
        *(float4*)(op + 4) = make_float4(v[4], v[5], v[6], v[7]);
    }
    if (tc == 0) {
        float* zp = g_hpZ + base + r0 + tr * 8;
        *(float4*)zp = make_float4(zs[0], zs[1], zs[2], zs[3]);
        *(float4*)(zp + 4) = make_float4(zs[4], zs[5], zs[6], zs[7]);
    }
}

// ---------------- 5b) reduce head partials -> xcat (LR 0.01) ----------------
__global__ void __launch_bounds__(256) reduce_heads_kernel() {
    const int idx = blockIdx.x * 256 + threadIdx.x;
    const int row = idx >> 8;
    const int cc = idx & 255;
    const int head = cc >> 6;
    const int col = cc & 63;
    float s = 0.f, z = 0.f;
#pragma unroll
    for (int sp = 0; sp < 4; sp++) {
        s += g_hp[((size_t)(sp * 4 + head) * NROWS + row) * 64 + col];
        z += g_hpZ[(sp * 4 + head) * NROWS + row];
    }
    float v = s / z;
    g_xcat[(size_t)row * 256 + cc] = fmaxf(v, 0.01f * v);
}

// ---------------- 6) h2 = xcat @ Wo ----------------
__global__ void __launch_bounds__(128) gemm2_kernel(const float* __restrict__ Wo) {
    __shared__ float Ws[256 * 16];
    const int tid = threadIdx.x;
    for (int i = tid; i < 4096; i += 128) Ws[i] = Wo[i];
    __syncthreads();
    const int row = blockIdx.x * 128 + tid;
    const float* xr = g_xcat + (size_t)row * 256;
    float acc[16];
#pragma unroll
    for (int j = 0; j < 16; j++) acc[j] = 0.f;
    for (int k = 0; k < 256; k += 4) {
        float4 xv = *(const float4*)(xr + k);
#pragma unroll
        for (int j = 0; j < 16; j++) {
            acc[j] += xv.x * Ws[(k + 0) * 16 + j];
            acc[j] += xv.y * Ws[(k + 1) * 16 + j];
            acc[j] += xv.z * Ws[(k + 2) * 16 + j];
            acc[j] += xv.w * Ws[(k + 3) * 16 + j];
        }
    }
#pragma unroll
    for (int j = 0; j < 16; j++) g_h2[row * 16 + j] = acc[j];
}

// ---------------- 7) final attention (z folded into k-loop) ----------------
__global__ void __launch_bounds__(128, 4) attn_final_gemm() {
    const int split = blockIdx.y;
    const int r0 = blockIdx.x * 128;
    const int tid = threadIdx.x;
    const int tr = tid >> 3;
    const int tc = tid & 7;
    const int jj = tid & 31;
    const int quarter = tid >> 5;

    __shared__ float Ps[32 * PSTRIDE];
    __shared__ float Hs[32 * 16];
    __shared__ float Aps[128], Ams[128];
    __shared__ unsigned mws[128];

    {
        float f1v = g_f1[4 * NROWS + r0 + tid];
        float gm = decf(g_gmaxu[4]);
        float s = f1v + gm;
        float m = fmaxf(s, 0.2f * s);
        Aps[tid] = ex2f(f1v - m);
        Ams[tid] = ex2f(0.2f * f1v - m);
    }
    unsigned long long acc[8];
#pragma unroll
    for (int r = 0; r < 8; r++) acc[r] = 0ull;
    float zs[8];
#pragma unroll
    for (int r = 0; r < 8; r++) zs[r] = 0.f;

    const int jbase = split * 1024;
    const size_t mrow = (size_t)(r0 + tid) * 256;

    float4 hpre = ((const float4*)(g_h2 + (size_t)jbase * 16))[tid];
    unsigned mwpre = g_mask[mrow + (jbase >> 5)];
    float2 bvpre = g_b2[4 * NROWS + jbase + jj];

    for (int ch = 0; ch < 32; ch++) {
        const int j0 = jbase + ch * 32;
        __syncthreads();
        ((float4*)Hs)[tid] = hpre;
        mws[tid] = mwpre;
        const float Bpr = bvpre.x, Bmr = bvpre.y;
        __syncthreads();
        {
            const int jn = (ch < 31) ? j0 + 32 : j0;
            hpre = ((const float4*)(g_h2 + (size_t)jn * 16))[tid];
            mwpre = g_mask[mrow + (jn >> 5)];
            bvpre = g_b2[4 * NROWS + jn + jj];
        }
        {
            const int i0 = quarter * 32;
            float* prow = Ps + jj * PSTRIDE;
#pragma unroll
            for (int ib = 0; ib < 32; ib += 4) {
                float pv[4];
#pragma unroll
                for (int ii = 0; ii < 4; ii++) {
                    const int i = i0 + ib + ii;
                    float v = fmaxf(Aps[i] * Bpr, Ams[i] * Bmr);
                    pv[ii] = ((mws[i] >> jj) & 1u) ? v : 0.f;
                }
                *(float4*)(prow + i0 + ib) = make_float4(pv[0], pv[1], pv[2], pv[3]);
            }
        }
        __syncthreads();
#pragma unroll 2
        for (int k = 0; k < 32; k++) {
            float4 pa = *(const float4*)(Ps + k * PSTRIDE + tr * 8);
            float4 pb = *(const float4*)(Ps + k * PSTRIDE + tr * 8 + 4);
            unsigned long long h0 = lds1u64(Hs + k * 16 + tc * 2);
            zs[0] += pa.x; zs[1] += pa.y; zs[2] += pa.z; zs[3] += pa.w;
            zs[4] += pb.x; zs[5] += pb.y; zs[6] += pb.z; zs[7] += pb.w;
            unsigned long long p2[8];
            p2[0] = pk2(pa.x, pa.x); p2[1] = pk2(pa.y, pa.y);
            p2[2] = pk2(pa.z, pa.z); p2[3] = pk2(pa.w, pa.w);
            p2[4] = pk2(pb.x, pb.x); p2[5] = pk2(pb.y, pb.y);
            p2[6] = pk2(pb.z, pb.z); p2[7] = pk2(pb.w, pb.w);
#pragma unroll
            for (int r = 0; r < 8; r++) fma2(acc[r], p2[r], h0);
        }
    }
#pragma unroll
    for (int r = 0; r < 8; r++) {
        const int row = r0 + tr * 8 + r;
        *(unsigned long long*)&g_part[((size_t)split * NROWS + row) * 16 + tc * 2] = acc[r];
    }
    if (tc == 0) {
        float* zp = g_partZ + split * NROWS + r0 + tr * 8;
        *(float4*)zp = make_float4(zs[0], zs[1], zs[2], zs[3]);
        *(float4*)(zp + 4) = make_float4(zs[4], zs[5], zs[6], zs[7]);
    }
}

// ---------------- 8) reduce partials -> output ----------------
__global__ void __launch_bounds__(256) reduce_kernel(float* __restrict__ out) {
    const int idx = blockIdx.x * 256 + threadIdx.x;
    const int row = idx >> 4;
    float s = 0.f, z = 0.f;
#pragma unroll
    for (int c = 0; c < 8; c++) {
        s += g_part[((size_t)c * NROWS + row) * 16 + (idx & 15)];
        z += g_partZ[c * NROWS + row];
    }
    out[idx] = s / z;
}

extern "C" void kernel_launch(void* const* d_in, const int* in_sizes, int n_in,
                              void* d_out, int out_size) {
    const float* x   = (const float*)d_in[0];
    const int*   adj = (const int*)d_in[1];
    const float* Wh  = (const float*)d_in[2];
    const float* ah  = (const float*)d_in[3];
    const float* Wo  = (const float*)d_in[4];
    const float* ao  = (const float*)d_in[5];
    float* out = (float*)d_out;

    gemm64_kernel<<<dim3(128, 4), 256>>>(x, Wh);      // 1: also inits g_gmaxu
    f1f2_heads_kernel<<<dim3(1024, 4), 256>>>(ah);    // 2: atomicMax gmax[0..3]
    pack_adj_kernel<<<2048, 256>>>(adj);              // 3
    attn_heads_gemm<<<dim3(64, 4, 4), 128>>>();       // 4  <- ncu capture slot
    reduce_heads_kernel<<<8192, 256>>>();             // 5
    gemm2_kernel<<<64, 128>>>(Wo);                    // 6
    f1f2_final_kernel<<<1024, 256>>>(ao);             // 7: atomicMax gmax[4]
    attn_final_gemm<<<dim3(64, 8), 128>>>();          // 8
    reduce_kernel<<<512, 256>>>(out);                 // 9
}

// round 17
// speedup vs baseline: 1.1534x; 1.1534x over previous
#include <cuda_runtime.h>
#include <cstdint>

#define NROWS 8192
#define L2E 1.44269504088896340736f

// ---------------- scratch ----------------
__device__ __align__(16) unsigned g_mask[NROWS * 256];   // 8 MB bitmask
__device__ __align__(16) float g_h[4 * NROWS * 64];      // per-head h = x@Wh
__device__ __align__(16) float g_xcat[NROWS * 256];      // concat LR(head outputs)
__device__ __align__(16) float g_h2[NROWS * 16];         // xcat@Wo
__device__ __align__(16) float g_f1[5 * NROWS];          // f1 * log2e per layer
__device__ __align__(16) float g_f2[5 * NROWS];          // f2 * log2e per layer
__device__ __align__(16) float2 g_b2[5 * NROWS];         // {2^f2, 2^(0.2 f2)}
__device__ unsigned g_gmaxu[5];                          // encoded global max of f2
__device__ __align__(16) float g_hp[16 * NROWS * 64];    // heads partials
__device__ __align__(16) float g_hpZ[16 * NROWS];
__device__ __align__(16) float g_part[8 * NROWS * 16];   // final-layer partials
__device__ __align__(16) float g_partZ[8 * NROWS];

// ---------------- helpers ----------------
__device__ __forceinline__ float ex2f(float x) {
    float r; asm("ex2.approx.ftz.f32 %0, %1;" : "=f"(r) : "f"(x)); return r;
}
__device__ __forceinline__ unsigned long long pk2(float a, float b) {
    unsigned long long r; asm("mov.b64 %0, {%1, %2};" : "=l"(r) : "f"(a), "f"(b)); return r;
}
__device__ __forceinline__ void up2(unsigned long long v, float& a, float& b) {
    asm("mov.b64 {%0, %1}, %2;" : "=f"(a), "=f"(b) : "l"(v));
}
__device__ __forceinline__ void fma2(unsigned long long& d, unsigned long long a, unsigned long long b) {
    asm("fma.rn.f32x2 %0, %1, %2, %0;" : "+l"(d) : "l"(a), "l"(b));
}
__device__ __forceinline__ void lds2u64(const float* p, unsigned long long& a, unsigned long long& b) {
    unsigned sa = (unsigned)__cvta_generic_to_shared(p);
    asm volatile("ld.shared.v2.u64 {%0, %1}, [%2];" : "=l"(a), "=l"(b) : "r"(sa));
}
__device__ __forceinline__ unsigned long long lds1u64(const float* p) {
    unsigned sa = (unsigned)__cvta_generic_to_shared(p);
    unsigned long long r;
    asm volatile("ld.shared.b64 %0, [%1];" : "=l"(r) : "r"(sa));
    return r;
}
__device__ __forceinline__ void cpa16(unsigned dst, const void* src) {
    asm volatile("cp.async.cg.shared.global [%0], [%1], 16;" :: "r"(dst), "l"(src));
}
__device__ __forceinline__ void cpa_commit() {
    asm volatile("cp.async.commit_group;" ::: "memory");
}
__device__ __forceinline__ void cpa_waitall() {
    asm volatile("cp.async.wait_group 0;" ::: "memory");
}
// order-preserving fp32 <-> uint for atomicMax
__device__ __forceinline__ unsigned encf(float f) {
    unsigned u = __float_as_uint(f);
    return (u & 0x80000000u) ? ~u : (u | 0x80000000u);
}
__device__ __forceinline__ float decf(unsigned e) {
    unsigned u = (e & 0x80000000u) ? (e ^ 0x80000000u) : ~e;
    return __uint_as_float(u);
}

// ---------------- 1) pack adjacency ----------------
__global__ void __launch_bounds__(256) pack_adj_kernel(const int* __restrict__ adj) {
    const int lane = threadIdx.x & 31;
    const int wid = (blockIdx.x * blockDim.x + threadIdx.x) >> 5;
    const int nWarps = (gridDim.x * blockDim.x) >> 5;
    for (int w = wid; w < NROWS * 256; w += nWarps) {
        int v = adj[(size_t)w * 32 + lane];
        unsigned b = __ballot_sync(0xffffffffu, v > 0);
        if (lane == 0) g_mask[w] = b;
    }
}

// ---------------- 2) h = x @ Wh[head] (FFMA2 row-pair), inits g_gmaxu --------
__global__ void __launch_bounds__(256) gemm64_kernel(const float* __restrict__ X,
                                                     const float* __restrict__ WhAll) {
    const int head = blockIdx.y;
    const float* W = WhAll + head * (512 * 64);
    float* C = g_h + head * (NROWS * 64);
    const int r0 = blockIdx.x * 64;
    const int tid = threadIdx.x;
    if (blockIdx.x == 0 && blockIdx.y == 0 && tid < 5) g_gmaxu[tid] = 0u;
    __shared__ float4 As4[512];
    __shared__ float4 Bs4[512];
    float* As = (float*)As4;
    float* Bs = (float*)Bs4;
    const int tr = tid >> 4, tc = tid & 15;
    const int lm = tid & 63, kg = tid >> 6;
    unsigned long long accP[2][4];
#pragma unroll
    for (int p = 0; p < 2; p++)
#pragma unroll
        for (int j = 0; j < 4; j++) accP[p][j] = 0ull;

    for (int kt = 0; kt < 512; kt += 32) {
        __syncthreads();
        const float* xb = X + (size_t)(r0 + lm) * 512 + kt + kg * 8;
        float4 a0 = ((const float4*)xb)[0];
        float4 a1 = ((const float4*)xb)[1];
        As[(kg * 8 + 0) * 64 + lm] = a0.x; As[(kg * 8 + 1) * 64 + lm] = a0.y;
        As[(kg * 8 + 2) * 64 + lm] = a0.z; As[(kg * 8 + 3) * 64 + lm] = a0.w;
        As[(kg * 8 + 4) * 64 + lm] = a1.x; As[(kg * 8 + 5) * 64 + lm] = a1.y;
        As[(kg * 8 + 6) * 64 + lm] = a1.z; As[(kg * 8 + 7) * 64 + lm] = a1.w;
        const float4* wsrc = (const float4*)(W + kt * 64);
        Bs4[tid] = wsrc[tid];
        Bs4[tid + 256] = wsrc[tid + 256];
        __syncthreads();
#pragma unroll
        for (int kk = 0; kk < 32; kk++) {
            unsigned long long ap0, ap1;
            lds2u64(As + kk * 64 + tr * 4, ap0, ap1);
            float4 bv = *(const float4*)(Bs + kk * 64 + tc * 4);
            unsigned long long b0 = pk2(bv.x, bv.x);
            unsigned long long b1 = pk2(bv.y, bv.y);
            unsigned long long b2 = pk2(bv.z, bv.z);
            unsigned long long b3 = pk2(bv.w, bv.w);
            fma2(accP[0][0], ap0, b0); fma2(accP[0][1], ap0, b1);
            fma2(accP[0][2], ap0, b2); fma2(accP[0][3], ap0, b3);
            fma2(accP[1][0], ap1, b0); fma2(accP[1][1], ap1, b1);
            fma2(accP[1][2], ap1, b2); fma2(accP[1][3], ap1, b3);
        }
    }
#pragma unroll
    for (int p = 0; p < 2; p++) {
        float lo[4], hi[4];
#pragma unroll
        for (int j = 0; j < 4; j++) up2(accP[p][j], lo[j], hi[j]);
        *(float4*)(C + (size_t)(r0 + tr * 4 + 2 * p) * 64 + tc * 4) =
            make_float4(lo[0], lo[1], lo[2], lo[3]);
        *(float4*)(C + (size_t)(r0 + tr * 4 + 2 * p + 1) * 64 + tc * 4) =
            make_float4(hi[0], hi[1], hi[2], hi[3]);
    }
}

// ---------------- 3) f1/f2 + B values + block-reduced gmax ----------------
__global__ void __launch_bounds__(256) f1f2_heads_kernel(const float* __restrict__ ah) {
    const int head = blockIdx.y;
    const float* H = g_h + head * (NROWS * 64);
    const float* a = ah + head * 128;
    const int lane = threadIdx.x & 31;
    const int warp = threadIdx.x >> 5;
    const int row = blockIdx.x * 8 + warp;
    __shared__ float bmax[8];
    float h0 = H[row * 64 + lane], h1 = H[row * 64 + 32 + lane];
    float s1 = h0 * a[lane] + h1 * a[32 + lane];
    float s2 = h0 * a[64 + lane] + h1 * a[96 + lane];
#pragma unroll
    for (int off = 16; off; off >>= 1) {
        s1 += __shfl_xor_sync(0xffffffffu, s1, off);
        s2 += __shfl_xor_sync(0xffffffffu, s2, off);
    }
    float f2v = s2 * L2E;
    if (lane == 0) {
        g_f1[head * NROWS + row] = s1 * L2E;
        g_f2[head * NROWS + row] = f2v;
        g_b2[head * NROWS + row] = make_float2(ex2f(f2v), ex2f(0.2f * f2v));
        bmax[warp] = f2v;
    }
    __syncthreads();
    if (threadIdx.x == 0) {
        float m = bmax[0];
#pragma unroll
        for (int i = 1; i < 8; i++) m = fmaxf(m, bmax[i]);
        atomicMax(&g_gmaxu[head], encf(m));
    }
}

__global__ void __launch_bounds__(256) f1f2_final_kernel(const float* __restrict__ ao) {
    const int lane = threadIdx.x & 31;
    const int warp = threadIdx.x >> 5;
    const int row = blockIdx.x * 8 + warp;
    __shared__ float bmax[8];
    float s1 = 0.f, s2 = 0.f;
    if (lane < 16) {
        float h = g_h2[row * 16 + lane];
        s1 = h * ao[lane];
        s2 = h * ao[16 + lane];
    }
#pragma unroll
    for (int off = 16; off; off >>= 1) {
        s1 += __shfl_xor_sync(0xffffffffu, s1, off);
        s2 += __shfl_xor_sync(0xffffffffu, s2, off);
    }
    float f2v = s2 * L2E;
    if (lane == 0) {
        g_f1[4 * NROWS + row] = s1 * L2E;
        g_f2[4 * NROWS + row] = f2v;
        g_b2[4 * NROWS + row] = make_float2(ex2f(f2v), ex2f(0.2f * f2v));
        bmax[warp] = f2v;
    }
    __syncthreads();
    if (threadIdx.x == 0) {
        float m = bmax[0];
#pragma unroll
        for (int i = 1; i < 8; i++) m = fmaxf(m, bmax[i]);
        atomicMax(&g_gmaxu[4], encf(m));
    }
}

// ---------------- 5) head attention: cp.async double-buffered H, unroll 4 ----
#define PSTRIDE 132
__global__ void __launch_bounds__(128, 4) attn_heads_gemm() {
    const int head = blockIdx.y;
    const int split = blockIdx.z;
    const int r0 = blockIdx.x * 128;
    const int tid = threadIdx.x;
    const int tr = tid >> 3;
    const int tc = tid & 7;
    const int jj = tid & 31;
    const int quarter = tid >> 5;

    __shared__ float Ps[32 * PSTRIDE];
    __shared__ float Hs[2][2048];   // double-buffered 32x64 tiles
    __shared__ float Aps[128], Ams[128];
    __shared__ unsigned mws[128];

    {
        float f1v = g_f1[head * NROWS + r0 + tid];
        float gm = decf(g_gmaxu[head]);
        float s = f1v + gm;
        float m = fmaxf(s, 0.2f * s);
        Aps[tid] = ex2f(f1v - m);
        Ams[tid] = ex2f(0.2f * f1v - m);
    }

    unsigned long long acc[8][4];
#pragma unroll
    for (int r = 0; r < 8; r++)
#pragma unroll
        for (int c = 0; c < 4; c++) acc[r][c] = 0ull;
    float zrow = 0.f;

    const int jbase = split * 2048;
    const float4* hsrc = (const float4*)(g_h + (size_t)head * NROWS * 64);
    const size_t mrow = (size_t)(r0 + tid) * 256;
    const unsigned hs0 = (unsigned)__cvta_generic_to_shared(&Hs[0][0]);
    const unsigned hs1 = (unsigned)__cvta_generic_to_shared(&Hs[1][0]);

    // kick chunk 0 into buffer 0
    {
        const float4* s = hsrc + (size_t)jbase * 16;
#pragma unroll
        for (int v = 0; v < 4; v++) cpa16(hs0 + (tid + 128 * v) * 16, s + tid + 128 * v);
        cpa_commit();
    }
    unsigned mwpre = g_mask[mrow + (jbase >> 5)];
    float2 bvpre = g_b2[head * NROWS + jbase + jj];

    for (int ch = 0; ch < 64; ch++) {
        const int j0 = jbase + ch * 32;
        const float* Hcur = Hs[ch & 1];
        const unsigned hnext = (ch & 1) ? hs0 : hs1;
        cpa_waitall();
        __syncthreads();           // cur H buffer + prev Ps consumers done
        mws[tid] = mwpre;
        const float Bpr = bvpre.x, Bmr = bvpre.y;
        __syncthreads();           // mws visible to build
        // issue next chunk's H into the other buffer (prev k-loop done with it)
        {
            const int jn = (ch < 63) ? j0 + 32 : j0;
            const float4* s = hsrc + (size_t)jn * 16;
#pragma unroll
            for (int v = 0; v < 4; v++) cpa16(hnext + (tid + 128 * v) * 16, s + tid + 128 * v);
            cpa_commit();
            mwpre = g_mask[mrow + (jn >> 5)];
            bvpre = g_b2[head * NROWS + jn + jj];
        }
        // build P (max-form)
        {
            const int i0 = quarter * 32;
            float* prow = Ps + jj * PSTRIDE;
#pragma unroll
            for (int ib = 0; ib < 32; ib += 4) {
                float pv[4];
#pragma unroll
                for (int ii = 0; ii < 4; ii++) {
                    const int i = i0 + ib + ii;
                    float v = fmaxf(Aps[i] * Bpr, Ams[i] * Bmr);
                    pv[ii] = ((mws[i] >> jj) & 1u) ? v : 0.f;
                }
                *(float4*)(prow + i0 + ib) = make_float4(pv[0], pv[1], pv[2], pv[3]);
            }
        }
        __syncthreads();           // Ps ready
#pragma unroll 4
        for (int k = 0; k < 32; k++) {
            float4 pa = *(const float4*)(Ps + k * PSTRIDE + tr * 8);
            float4 pb = *(const float4*)(Ps + k * PSTRIDE + tr * 8 + 4);
            unsigned long long h0, h1, h2, h3;
            lds2u64(Hcur + k * 64 + tc * 8, h0, h1);
            lds2u64(Hcur + k * 64 + tc * 8 + 4, h2, h3);
            unsigned long long p2[8];
            p2[0] = pk2(pa.x, pa.x); p2[1] = pk2(pa.y, pa.y);
            p2[2] = pk2(pa.z, pa.z); p2[3] = pk2(pa.w, pa.w);
            p2[4] = pk2(pb.x, pb.x); p2[5] = pk2(pb.y, pb.y);
            p2[6] = pk2(pb.z, pb.z); p2[7] = pk2(pb.w, pb.w);
#pragma unroll
            for (int r = 0; r < 8; r++) {
                fma2(acc[r][0], p2[r], h0);
                fma2(acc[r][1], p2[r], h1);
                fma2(acc[r][2], p2[r], h2);
                fma2(acc[r][3], p2[r], h3);
            }
        }
        // z pass (coalesced re-read; proven cheap)
        {
            float zs = 0.f;
#pragma unroll 8
            for (int k = 0; k < 32; k++) zs += Ps[k * PSTRIDE + tid];
            zrow += zs;
        }
    }
    const int base = (split * 4 + head) * NROWS;
#pragma unroll
    for (int r = 0; r < 8; r++) {
        const int row = r0 + tr * 8 + r;
        float v[8];
        up2(acc[r][0], v[0], v[1]);
        up2(acc[r][1], v[2], v[3]);
        up2(acc[r][2], v[4], v[5]);
        up2(acc[r][3], v[6], v[7]);
        float* op = g_hp + ((size_t)base + row) * 64 + tc * 8;
        *(float4*)op = make_float4(v[0], v[1], v[2], v[3]);
        *(float4*)(op + 4) = make_float4(v[4], v[5], v[6], v[7]);
    }
    g_hpZ[base + r0 + tid] = zrow;
}

// ---------------- 5b) reduce head partials -> xcat (LR 0.01) ----------------
__global__ void __launch_bounds__(256) reduce_heads_kernel() {
    const int idx = blockIdx.x * 256 + threadIdx.x;
    const int row = idx >> 8;
    const int cc = idx & 255;
    const int head = cc >> 6;
    const int col = cc & 63;
    float s = 0.f, z = 0.f;
#pragma unroll
    for (int sp = 0; sp < 4; sp++) {
        s += g_hp[((size_t)(sp * 4 + head) * NROWS + row) * 64 + col];
        z += g_hpZ[(sp * 4 + head) * NROWS + row];
    }
    float v = s / z;
    g_xcat[(size_t)row * 256 + cc] = fmaxf(v, 0.01f * v);
}

// ---------------- 6) h2 = xcat @ Wo ----------------
__global__ void __launch_bounds__(128) gemm2_kernel(const float* __restrict__ Wo) {
    __shared__ float Ws[256 * 16];
    const int tid = threadIdx.x;
    for (int i = tid; i < 4096; i += 128) Ws[i] = Wo[i];
    __syncthreads();
    const int row = blockIdx.x * 128 + tid;
    const float* xr = g_xcat + (size_t)row * 256;
    float acc[16];
#pragma unroll
    for (int j = 0; j < 16; j++) acc[j] = 0.f;
    for (int k = 0; k < 256; k += 4) {
        float4 xv = *(const float4*)(xr + k);
#pragma unroll
        for (int j = 0; j < 16; j++) {
            acc[j] += xv.x * Ws[(k + 0) * 16 + j];
            acc[j] += xv.y * Ws[(k + 1) * 16 + j];
            acc[j] += xv.z * Ws[(k + 2) * 16 + j];
            acc[j] += xv.w * Ws[(k + 3) * 16 + j];
        }
    }
#pragma unroll
    for (int j = 0; j < 16; j++) g_h2[row * 16 + j] = acc[j];
}

// ---------------- 7) final attention (R15 version: reg prefetch + z pass) ----
__global__ void __launch_bounds__(128) attn_final_gemm() {
    const int split = blockIdx.y;
    const int r0 = blockIdx.x * 128;
    const int tid = threadIdx.x;
    const int tr = tid >> 3;
    const int tc = tid & 7;
    const int jj = tid & 31;
    const int quarter = tid >> 5;

    __shared__ float Ps[32 * PSTRIDE];
    __shared__ float Hs[32 * 16];
    __shared__ float Aps[128], Ams[128];
    __shared__ unsigned mws[128];

    {
        float f1v = g_f1[4 * NROWS + r0 + tid];
        float gm = decf(g_gmaxu[4]);
        float s = f1v + gm;
        float m = fmaxf(s, 0.2f * s);
        Aps[tid] = ex2f(f1v - m);
        Ams[tid] = ex2f(0.2f * f1v - m);
    }
    unsigned long long acc[8];
#pragma unroll
    for (int r = 0; r < 8; r++) acc[r] = 0ull;
    float zrow = 0.f;

    const int jbase = split * 1024;
    const size_t mrow = (size_t)(r0 + tid) * 256;

    float4 hpre = ((const float4*)(g_h2 + (size_t)jbase * 16))[tid];
    unsigned mwpre = g_mask[mrow + (jbase >> 5)];
    float2 bvpre = g_b2[4 * NROWS + jbase + jj];

    for (int ch = 0; ch < 32; ch++) {
        const int j0 = jbase + ch * 32;
        __syncthreads();
        ((float4*)Hs)[tid] = hpre;
        mws[tid] = mwpre;
        const float Bpr = bvpre.x, Bmr = bvpre.y;
        __syncthreads();
        {
            const int jn = (ch < 31) ? j0 + 32 : j0;
            hpre = ((const float4*)(g_h2 + (size_t)jn * 16))[tid];
            mwpre = g_mask[mrow + (jn >> 5)];
            bvpre = g_b2[4 * NROWS + jn + jj];
        }
        {
            const int i0 = quarter * 32;
            float* prow = Ps + jj * PSTRIDE;
#pragma unroll
            for (int ib = 0; ib < 32; ib += 4) {
                float pv[4];
#pragma unroll
                for (int ii = 0; ii < 4; ii++) {
                    const int i = i0 + ib + ii;
                    float v = fmaxf(Aps[i] * Bpr, Ams[i] * Bmr);
                    pv[ii] = ((mws[i] >> jj) & 1u) ? v : 0.f;
                }
                *(float4*)(prow + i0 + ib) = make_float4(pv[0], pv[1], pv[2], pv[3]);
            }
        }
        __syncthreads();
#pragma unroll 2
        for (int k = 0; k < 32; k++) {
            float4 pa = *(const float4*)(Ps + k * PSTRIDE + tr * 8);
            float4 pb = *(const float4*)(Ps + k * PSTRIDE + tr * 8 + 4);
            unsigned long long h0 = lds1u64(Hs + k * 16 + tc * 2);
            unsigned long long p2[8];
            p2[0] = pk2(pa.x, pa.x); p2[1] = pk2(pa.y, pa.y);
            p2[2] = pk2(pa.z, pa.z); p2[3] = pk2(pa.w, pa.w);
            p2[4] = pk2(pb.x, pb.x); p2[5] = pk2(pb.y, pb.y);
            p2[6] = pk2(pb.z, pb.z); p2[7] = pk2(pb.w, pb.w);
#pragma unroll
            for (int r = 0; r < 8; r++) fma2(acc[r], p2[r], h0);
        }
        {
            float zs = 0.f;
#pragma unroll 8
            for (int k = 0; k < 32; k++) zs += Ps[k * PSTRIDE + tid];
            zrow += zs;
        }
    }
#pragma unroll
    for (int r = 0; r < 8; r++) {
        const int row = r0 + tr * 8 + r;
        *(unsigned long long*)&g_part[((size_t)split * NROWS + row) * 16 + tc * 2] = acc[r];
    }
    g_partZ[split * NROWS + r0 + tid] = zrow;
}

// ---------------- 8) reduce partials -> output ----------------
__global__ void __launch_bounds__(256) reduce_kernel(float* __restrict__ out) {
    const int idx = blockIdx.x * 256 + threadIdx.x;
    const int row = idx >> 4;
    float s = 0.f, z = 0.f;
#pragma unroll
    for (int c = 0; c < 8; c++) {
        s += g_part[((size_t)c * NROWS + row) * 16 + (idx & 15)];
        z += g_partZ[c * NROWS + row];
    }
    out[idx] = s / z;
}

extern "C" void kernel_launch(void* const* d_in, const int* in_sizes, int n_in,
                              void* d_out, int out_size) {
    const float* x   = (const float*)d_in[0];
    const int*   adj = (const int*)d_in[1];
    const float* Wh  = (const float*)d_in[2];
    const float* ah  = (const float*)d_in[3];
    const float* Wo  = (const float*)d_in[4];
    const float* ao  = (const float*)d_in[5];
    float* out = (float*)d_out;

    gemm64_kernel<<<dim3(128, 4), 256>>>(x, Wh);      // 1: also inits g_gmaxu
    f1f2_heads_kernel<<<dim3(1024, 4), 256>>>(ah);    // 2: atomicMax gmax[0..3]
    pack_adj_kernel<<<2048, 256>>>(adj);              // 3
    attn_heads_gemm<<<dim3(64, 4, 4), 128>>>();       // 4  <- ncu capture slot
    reduce_heads_kernel<<<8192, 256>>>();             // 5
    gemm2_kernel<<<64, 128>>>(Wo);                    // 6
    f1f2_final_kernel<<<1024, 256>>>(ao);             // 7: atomicMax gmax[4]
    attn_final_gemm<<<dim3(64, 8), 128>>>();          // 8
    reduce_kernel<<<512, 256>>>(out);                 // 9
}